// round 14
// baseline (speedup 1.0000x reference)
#include <cuda_runtime.h>
#include <cuda_bf16.h>
#include <cstdint>

#define NB      32
#define NRINGS  10
#define NANG    36
#define NPTS    (NRINGS * NANG)     // 360
#define NTGT    16384
#define TPB     (NRINGS * 32)       // 320 threads: warp = ring
#define NBLK    444                 // 148 SMs x 3 resident -> one wave
#define NBIG    392                 // batches 0..27: 14 blocks x 37 groups
#define NG_BIG  37                  // 14*37*32 >= 16384 (dup-clamped tail)
#define NG_SML  40                  // 13*40*32 >= 16384
#define MAXT    (NG_SML * 32)       // 1280 staged targets
#define NSAMP_IT 2                  // 64-target exact sample per warp

// Monotone-encoded running max of -d2 per (batch,point). Zero = -inf sentinel;
// last block resets after the reduce so graph replays see a clean state.
__device__ unsigned int g_keys[NB * NPTS];
__device__ unsigned int g_count;

__device__ __forceinline__ unsigned int enc_f32(float f) {
    unsigned int u = __float_as_uint(f);
    return ((int)u < 0) ? ~u : (u | 0x80000000u);
}
__device__ __forceinline__ float dec_f32(unsigned int k) {
    unsigned int u = ((int)k < 0) ? (k & 0x7FFFFFFFu) : ~k;
    return __uint_as_float(u);
}

// cos/sin magnitudes (10..40 deg); all appear as FFMA immediates.
#define K_C1 0.9848077530f
#define K_S1 0.1736481777f
#define K_C2 0.9396926208f
#define K_S2 0.3420201433f
#define K_C3 0.8660254038f
#define K_S3 0.5f
#define K_C4 0.7660444431f
#define K_S4 0.6427876097f

// Full-circle eval (sample phase): pairs (a,36-a) share cos.
#define PAIR2(IA, IB, CV, SV)                        \
    { float P = fmaf(CV, U, Acc);                    \
      m[IA] = fminf(m[IA], fmaf( SV, V, P));         \
      m[IB] = fminf(m[IB], fmaf(-SV, V, P)); }

__device__ __forceinline__ void eval36(float m[NANG], float U, float V, float Acc) {
    m[ 0] = fminf(m[ 0], Acc + U);
    m[18] = fminf(m[18], Acc - U);
    m[ 9] = fminf(m[ 9], Acc + V);
    m[27] = fminf(m[27], Acc - V);
    PAIR2( 1, 35,  K_C1, K_S1)
    PAIR2( 2, 34,  K_C2, K_S2)
    PAIR2( 3, 33,  K_C3, K_S3)
    PAIR2( 4, 32,  K_C4, K_S4)
    PAIR2( 5, 31,  K_S4, K_C4)
    PAIR2( 6, 30,  K_S3, K_C3)
    PAIR2( 7, 29,  K_S2, K_C2)
    PAIR2( 8, 28,  K_S1, K_C1)
    PAIR2(10, 26, -K_S1, K_C1)
    PAIR2(11, 25, -K_S2, K_C2)
    PAIR2(12, 24, -K_S3, K_C3)
    PAIR2(13, 23, -K_S4, K_C4)
    PAIR2(14, 22, -K_C4, K_S4)
    PAIR2(15, 21, -K_C3, K_S3)
    PAIR2(16, 20, -K_C2, K_S2)
    PAIR2(17, 19, -K_C1, K_S1)
}

// Upper half {0..18}: pairs (a, 18-a) share sin. P = fma(S,V,Acc); then +/-C*U.
#define HPAIR(IA, IB, SV, CV)                        \
    { float P = fmaf(SV, V, Acc);                    \
      m[IA] = fminf(m[IA], fmaf( CV, U, P));         \
      m[IB] = fminf(m[IB], fmaf(-CV, U, P)); }

__device__ __forceinline__ void evalA(float m[NANG], float U, float V, float Acc) {
    m[ 0] = fminf(m[ 0], Acc + U);
    m[ 9] = fminf(m[ 9], Acc + V);
    m[18] = fminf(m[18], Acc - U);
    HPAIR( 1, 17, K_S1, K_C1)
    HPAIR( 2, 16, K_S2, K_C2)
    HPAIR( 3, 15, K_S3, K_C3)
    HPAIR( 4, 14, K_S4, K_C4)
    HPAIR( 5, 13, K_C4, K_S4)   // sin50=cos40, cos50=sin40
    HPAIR( 6, 12, K_C3, K_S3)
    HPAIR( 7, 11, K_C2, K_S2)
    HPAIR( 8, 10, K_C1, K_S1)
}

// Lower half {19..35}: pairs (35-k, 19+k) share -sin.
__device__ __forceinline__ void evalB(float m[NANG], float U, float V, float Acc) {
    m[27] = fminf(m[27], Acc - V);
    HPAIR(35, 19, -K_S1, K_C1)
    HPAIR(34, 20, -K_S2, K_C2)
    HPAIR(33, 21, -K_S3, K_C3)
    HPAIR(32, 22, -K_S4, K_C4)
    HPAIR(31, 23, -K_C4, K_S4)
    HPAIR(30, 24, -K_C3, K_S3)
    HPAIR(29, 25, -K_C2, K_S2)
    HPAIR(28, 26, -K_C1, K_S1)
}

// Filter + compact + dense eval for one half. HALF=0 -> upper arc (sin >= 0).
// min over arc of (C*U + S*V) = -W iff the minimizing direction -(U,V)/W lies
// in the arc: HALF 0 needs -V >= 0 (V <= 0); HALF 1 needs -V <= 0 (V >= 0).
// Otherwise endpoint bound -|U| (endpoints theta = 0 / 180).
template<int NG, int HALF>
__device__ __forceinline__ void half_pass(
    float m[NANG], const float4* __restrict__ sm,
    unsigned short* __restrict__ sidx,
    int lane, float r, float py, float Kr, float ub)
{
    unsigned cnt = 0;
    #pragma unroll 2
    for (int it = NSAMP_IT; it < NG; it++) {
        const int i = it * 32 + lane;
        float4 v  = sm[i];
        float Acc = fmaf(py, v.y, v.w) + Kr;
        float U   = r * v.x;
        float V   = r * v.z;
        float U2  = U * U;
        float W2  = fmaf(V, V, U2);
        bool  in  = (HALF == 0) ? (V <= 0.0f) : (V >= 0.0f);   // FIXED sign
        float B2  = in ? W2 : U2;
        float t   = Acc - ub;
        bool keep = (t <= 0.0f) || (t * t <= B2);
        unsigned mask = __ballot_sync(0xffffffffu, keep);
        if (keep) {
            unsigned pos = cnt + __popc(mask & ((1u << lane) - 1u));
            sidx[pos] = (unsigned short)i;
        }
        cnt += __popc(mask);
    }
    for (unsigned k = lane; k < cnt; k += 32) {
        float4 v  = sm[sidx[k]];
        float Acc = fmaf(py, v.y, v.w) + Kr;
        float U   = r * v.x;
        float V   = r * v.z;
        if (HALF == 0) evalA(m, U, V, Acc);
        else           evalB(m, U, V, Acc);
    }
}

template<int NG>
__device__ __forceinline__ void run_warp(
    float m[NANG], const float4* __restrict__ sm,
    unsigned short* __restrict__ sidx,
    int lane, float r, float py, float Kr)
{
    // ---- Phase 1: exact sample on first 64 targets (all 36 angles) ----
    #pragma unroll
    for (int it = 0; it < NSAMP_IT; it++) {
        float4 v  = sm[it * 32 + lane];
        float Acc = fmaf(py, v.y, v.w) + Kr;
        float U   = r * v.x;
        float V   = r * v.z;
        eval36(m, U, V, Acc);
    }

    // ---- Phase 2: per-half ubs = max over half's angles of warp-min ----
    const float NINF = -__int_as_float(0x7f800000);
    float ubA = NINF, ubB = NINF;
    #pragma unroll
    for (int a = 0; a < NANG; a++) {
        float x = m[a];
        #pragma unroll
        for (int o = 16; o > 0; o >>= 1)
            x = fminf(x, __shfl_xor_sync(0xffffffffu, x, o));
        if (a <= 18) ubA = fmaxf(ubA, x);
        else         ubB = fmaxf(ubB, x);
    }
    ubA = fmaf(1e-5f, fabsf(ubA), ubA) + 1e-4f;
    ubB = fmaf(1e-5f, fabsf(ubB), ubB) + 1e-4f;

    // ---- Phase 3/4 per half (sequential; shared survivor buffer) ----
    half_pass<NG, 0>(m, sm, sidx, lane, r, py, Kr, ubA);
    half_pass<NG, 1>(m, sm, sidx, lane, r, py, Kr, ubB);
}

__global__ void __launch_bounds__(TPB)
chamfer_fused_kernel(const float* __restrict__ pred,
                     const float* __restrict__ target,
                     float* __restrict__ out)
{
    __shared__ float4 sm[MAXT];                       // 20 KB
    __shared__ unsigned short sidx[NRINGS][MAXT];     // 25.6 KB survivor indices
    __shared__ float  wsum[NRINGS];
    __shared__ unsigned int is_last;

    const int bid = blockIdx.x;
    const int tid = threadIdx.x;

    int batch, wb, ng;
    if (bid < NBIG) { batch = bid / 14;            wb = bid - batch * 14;  ng = NG_BIG; }
    else            { int e = bid - NBIG; int q = e / 13;
                      batch = 28 + q;              wb = e - q * 13;        ng = NG_SML; }

    const int start = wb * ng * 32;
    const int n     = ng * 32;

    // Stage + preprocess (clamped tail): (2tx-0.08, -2ty, -2tz, t2-0.08tx)
    const float* tg = target + (size_t)batch * NTGT * 3;
    for (int i = tid; i < n; i += TPB) {
        int gi = min(start + i, NTGT - 1);
        float tx = tg[gi * 3 + 0];
        float ty = tg[gi * 3 + 1];
        float tz = tg[gi * 3 + 2];
        float t2 = tx * tx + ty * ty + tz * tz;
        sm[i] = make_float4(2.0f * tx - 0.08f, -2.0f * ty, -2.0f * tz,
                            fmaf(-0.08f, tx, t2));
    }
    __syncthreads();

    const int ring = tid >> 5;
    const int lane = tid & 31;

    const float r  = pred[batch * NRINGS + ring];
    const float py = 0.15f * (float)ring - 0.7f;
    const float Kr = fmaf(r, r, fmaf(py, py, 0.0016f));
    const unsigned int pbase = (unsigned)(batch * NPTS + ring * NANG);
    const float INF = __int_as_float(0x7f800000);

    float m[NANG];
    #pragma unroll
    for (int a = 0; a < NANG; a++) m[a] = INF;

    if (ng == NG_BIG) run_warp<NG_BIG>(m, sm, sidx[ring], lane, r, py, Kr);
    else              run_warp<NG_SML>(m, sm, sidx[ring], lane, r, py, Kr);

    // Final fold: butterfly min per angle, REDG.MAX into g_keys.
    #pragma unroll
    for (int a = 0; a < NANG; a++) {
        float x = m[a];
        #pragma unroll
        for (int o = 16; o > 0; o >>= 1)
            x = fminf(x, __shfl_xor_sync(0xffffffffu, x, o));
        if (lane == (a & 31))
            atomicMax(&g_keys[pbase + a], enc_f32(-x));
    }

    // ---- last-block finalize (fused) ----
    __threadfence();
    if (tid == 0)
        is_last = (atomicAdd(&g_count, 1u) == (unsigned)(NBLK - 1));
    __syncthreads();
    if (!is_last) return;
    __threadfence();

    uint4* keys4 = (uint4*)g_keys;
    const int n4 = (NB * NPTS) / 4;     // 2880
    float s = 0.0f;
    for (int i = tid; i < n4; i += TPB) {
        uint4 k = keys4[i];
        s += fmaxf(-dec_f32(k.x), 0.0f);
        s += fmaxf(-dec_f32(k.y), 0.0f);
        s += fmaxf(-dec_f32(k.z), 0.0f);
        s += fmaxf(-dec_f32(k.w), 0.0f);
    }
    #pragma unroll
    for (int o = 16; o > 0; o >>= 1) s += __shfl_down_sync(0xffffffffu, s, o);
    if (lane == 0) wsum[ring] = s;
    __syncthreads();
    if (tid == 0) {
        float tot = 0.0f;
        #pragma unroll
        for (int w = 0; w < NRINGS; w++) tot += wsum[w];
        out[0] = tot / (float)(NB * NPTS);
    }
    __syncthreads();   // all g_keys reads complete before reset

    const uint4 z4 = make_uint4(0u, 0u, 0u, 0u);
    for (int i = tid; i < n4; i += TPB) keys4[i] = z4;
    if (tid == 0) g_count = 0u;
}

extern "C" void kernel_launch(void* const* d_in, const int* in_sizes, int n_in,
                              void* d_out, int out_size) {
    const float* pred   = (const float*)d_in[0];   // (32, 10)
    const float* target = (const float*)d_in[1];   // (32, 16384, 3)
    float* out = (float*)d_out;

    chamfer_fused_kernel<<<NBLK, TPB>>>(pred, target, out);
}

// round 15
// speedup vs baseline: 1.0010x; 1.0010x over previous
#include <cuda_runtime.h>
#include <cuda_bf16.h>
#include <cstdint>

#define NB      32
#define NRINGS  10
#define NANG    36
#define NPTS    (NRINGS * NANG)     // 360
#define NTGT    16384
#define TPB     (NRINGS * 32)       // 320 threads: warp = ring
#define NBLK    444                 // 148 SMs x 3 resident -> one wave
#define NBIG    392                 // batches 0..27: 14 blocks x 37 groups
#define NG_BIG  37                  // 14*37*32 >= 16384 (dup-clamped tail)
#define NG_SML  40                  // 13*40*32 >= 16384
#define MAXT    (NG_SML * 32)       // 1280 staged targets
#define NSAMP_IT 4                  // 128-target exact sample per warp

// Monotone-encoded running max of -d2 per (batch,point). Zero = -inf sentinel;
// last block resets after the reduce so graph replays see a clean state.
__device__ unsigned int g_keys[NB * NPTS];
__device__ unsigned int g_count;

__device__ __forceinline__ unsigned int enc_f32(float f) {
    unsigned int u = __float_as_uint(f);
    return ((int)u < 0) ? ~u : (u | 0x80000000u);
}
__device__ __forceinline__ float dec_f32(unsigned int k) {
    unsigned int u = ((int)k < 0) ? (k & 0x7FFFFFFFu) : ~k;
    return __uint_as_float(u);
}

// cos/sin magnitudes (10..40 deg); all appear as FFMA immediates.
#define K_C1 0.9848077530f
#define K_S1 0.1736481777f
#define K_C2 0.9396926208f
#define K_S2 0.3420201433f
#define K_C3 0.8660254038f
#define K_S3 0.5f
#define K_C4 0.7660444431f
#define K_S4 0.6427876097f

// Full-circle eval (sample + bail paths): pairs (a,36-a) share cos.
#define PAIR2(IA, IB, CV, SV)                        \
    { float P = fmaf(CV, U, Acc);                    \
      m[IA] = fminf(m[IA], fmaf( SV, V, P));         \
      m[IB] = fminf(m[IB], fmaf(-SV, V, P)); }

__device__ __forceinline__ void eval36(float m[NANG], float U, float V, float Acc) {
    m[ 0] = fminf(m[ 0], Acc + U);
    m[18] = fminf(m[18], Acc - U);
    m[ 9] = fminf(m[ 9], Acc + V);
    m[27] = fminf(m[27], Acc - V);
    PAIR2( 1, 35,  K_C1, K_S1)
    PAIR2( 2, 34,  K_C2, K_S2)
    PAIR2( 3, 33,  K_C3, K_S3)
    PAIR2( 4, 32,  K_C4, K_S4)
    PAIR2( 5, 31,  K_S4, K_C4)
    PAIR2( 6, 30,  K_S3, K_C3)
    PAIR2( 7, 29,  K_S2, K_C2)
    PAIR2( 8, 28,  K_S1, K_C1)
    PAIR2(10, 26, -K_S1, K_C1)
    PAIR2(11, 25, -K_S2, K_C2)
    PAIR2(12, 24, -K_S3, K_C3)
    PAIR2(13, 23, -K_S4, K_C4)
    PAIR2(14, 22, -K_C4, K_S4)
    PAIR2(15, 21, -K_C3, K_S3)
    PAIR2(16, 20, -K_C2, K_S2)
    PAIR2(17, 19, -K_C1, K_S1)
}

// Upper half {0..18}: pairs (a, 18-a) share sin. P = fma(S,V,Acc); then +/-C*U.
#define HPAIR(IA, IB, SV, CV)                        \
    { float P = fmaf(SV, V, Acc);                    \
      m[IA] = fminf(m[IA], fmaf( CV, U, P));         \
      m[IB] = fminf(m[IB], fmaf(-CV, U, P)); }

__device__ __forceinline__ void evalA(float m[NANG], float U, float V, float Acc) {
    m[ 0] = fminf(m[ 0], Acc + U);
    m[ 9] = fminf(m[ 9], Acc + V);
    m[18] = fminf(m[18], Acc - U);
    HPAIR( 1, 17, K_S1, K_C1)
    HPAIR( 2, 16, K_S2, K_C2)
    HPAIR( 3, 15, K_S3, K_C3)
    HPAIR( 4, 14, K_S4, K_C4)
    HPAIR( 5, 13, K_C4, K_S4)
    HPAIR( 6, 12, K_C3, K_S3)
    HPAIR( 7, 11, K_C2, K_S2)
    HPAIR( 8, 10, K_C1, K_S1)
}

// Lower half {19..35}: pairs (35-k, 19+k) share -sin.
__device__ __forceinline__ void evalB(float m[NANG], float U, float V, float Acc) {
    m[27] = fminf(m[27], Acc - V);
    HPAIR(35, 19, -K_S1, K_C1)
    HPAIR(34, 20, -K_S2, K_C2)
    HPAIR(33, 21, -K_S3, K_C3)
    HPAIR(32, 22, -K_S4, K_C4)
    HPAIR(31, 23, -K_C4, K_S4)
    HPAIR(30, 24, -K_C3, K_S3)
    HPAIR(29, 25, -K_C2, K_S2)
    HPAIR(28, 26, -K_C1, K_S1)
}

// Sample, per-half ub, merged filter (dual-ended compaction), dense per half.
// Arc minimum of (C*U+S*V): -W iff -(U,V) dir in arc (half A: V<=0; B: V>=0),
// else endpoint bound -|U|.
template<int NG>
__device__ __forceinline__ void run_warp(
    float m[NANG], const float4* __restrict__ sm,
    unsigned short* __restrict__ sidx,
    int lane, float r, float py, float Kr)
{
    // ---- Phase 1: exact sample on first 128 targets (all 36 angles) ----
    #pragma unroll
    for (int it = 0; it < NSAMP_IT; it++) {
        float4 v  = sm[it * 32 + lane];
        float Acc = fmaf(py, v.y, v.w) + Kr;
        float U   = r * v.x;
        float V   = r * v.z;
        eval36(m, U, V, Acc);
    }

    // ---- Phase 2: per-half ubs = max over half's angles of warp-min ----
    const float NINF = -__int_as_float(0x7f800000);
    float ubA = NINF, ubB = NINF;
    #pragma unroll
    for (int a = 0; a < NANG; a++) {
        float x = m[a];
        #pragma unroll
        for (int o = 16; o > 0; o >>= 1)
            x = fminf(x, __shfl_xor_sync(0xffffffffu, x, o));
        if (a <= 18) ubA = fmaxf(ubA, x);
        else         ubB = fmaxf(ubB, x);
    }
    ubA = fmaf(1e-5f, fabsf(ubA), ubA) + 1e-4f;
    ubB = fmaf(1e-5f, fabsf(ubB), ubB) + 1e-4f;

    // ---- Phase 3: single merged filter; A compacts from front, B from back ----
    unsigned cntA = 0, cntB = 0;
    const unsigned lt = (1u << lane) - 1u;
    #pragma unroll 2
    for (int it = NSAMP_IT; it < NG; it++) {
        const int i = it * 32 + lane;
        float4 v  = sm[i];
        float Acc = fmaf(py, v.y, v.w) + Kr;
        float U   = r * v.x;
        float V   = r * v.z;
        float U2  = U * U;
        float W2  = fmaf(V, V, U2);
        float B2A = (V <= 0.0f) ? W2 : U2;
        float B2B = (V >= 0.0f) ? W2 : U2;
        float tA  = Acc - ubA;
        float tB  = Acc - ubB;
        bool keepA = (tA <= 0.0f) || (tA * tA <= B2A);
        bool keepB = (tB <= 0.0f) || (tB * tB <= B2B);
        unsigned mA = __ballot_sync(0xffffffffu, keepA);
        unsigned mB = __ballot_sync(0xffffffffu, keepB);
        unsigned nA = __popc(mA), nB = __popc(mB);
        if (cntA + cntB + nA + nB > (unsigned)MAXT) {
            // Pruning failed: direct full eval of this and all remaining iters.
            for (int jt = it; jt < NG; jt++) {
                float4 w  = sm[jt * 32 + lane];
                float Ac2 = fmaf(py, w.y, w.w) + Kr;
                float Uu  = r * w.x;
                float Vv  = r * w.z;
                eval36(m, Uu, Vv, Ac2);
            }
            break;
        }
        if (keepA) sidx[cntA + __popc(mA & lt)] = (unsigned short)i;
        if (keepB) sidx[(unsigned)MAXT - 1u - (cntB + __popc(mB & lt))] = (unsigned short)i;
        cntA += nA; cntB += nB;
    }

    // ---- Phase 4: dense eval per half on survivors ----
    for (unsigned k = lane; k < cntA; k += 32) {
        float4 v  = sm[sidx[k]];
        float Acc = fmaf(py, v.y, v.w) + Kr;
        float U   = r * v.x;
        float V   = r * v.z;
        evalA(m, U, V, Acc);
    }
    for (unsigned k = lane; k < cntB; k += 32) {
        float4 v  = sm[(unsigned)MAXT - 1u - k < (unsigned)MAXT ? sidx[(unsigned)MAXT - 1u - k] : 0];
        float Acc = fmaf(py, v.y, v.w) + Kr;
        float U   = r * v.x;
        float V   = r * v.z;
        evalB(m, U, V, Acc);
    }
}

__global__ void __launch_bounds__(TPB, 3)
chamfer_fused_kernel(const float* __restrict__ pred,
                     const float* __restrict__ target,
                     float* __restrict__ out)
{
    __shared__ float4 sm[MAXT];                       // 20 KB
    __shared__ unsigned short sidx[NRINGS][MAXT];     // 25.6 KB survivor indices
    __shared__ float  wsum[NRINGS];
    __shared__ unsigned int is_last;

    const int bid = blockIdx.x;
    const int tid = threadIdx.x;

    int batch, wb, ng;
    if (bid < NBIG) { batch = bid / 14;            wb = bid - batch * 14;  ng = NG_BIG; }
    else            { int e = bid - NBIG; int q = e / 13;
                      batch = 28 + q;              wb = e - q * 13;        ng = NG_SML; }

    const int start = wb * ng * 32;
    const int n     = ng * 32;

    // Stage + preprocess (clamped tail): (2tx-0.08, -2ty, -2tz, t2-0.08tx)
    const float* tg = target + (size_t)batch * NTGT * 3;
    for (int i = tid; i < n; i += TPB) {
        int gi = min(start + i, NTGT - 1);
        float tx = tg[gi * 3 + 0];
        float ty = tg[gi * 3 + 1];
        float tz = tg[gi * 3 + 2];
        float t2 = tx * tx + ty * ty + tz * tz;
        sm[i] = make_float4(2.0f * tx - 0.08f, -2.0f * ty, -2.0f * tz,
                            fmaf(-0.08f, tx, t2));
    }
    __syncthreads();

    const int ring = tid >> 5;
    const int lane = tid & 31;

    const float r  = pred[batch * NRINGS + ring];
    const float py = 0.15f * (float)ring - 0.7f;
    const float Kr = fmaf(r, r, fmaf(py, py, 0.0016f));
    const unsigned int pbase = (unsigned)(batch * NPTS + ring * NANG);
    const float INF = __int_as_float(0x7f800000);

    float m[NANG];
    #pragma unroll
    for (int a = 0; a < NANG; a++) m[a] = INF;

    if (ng == NG_BIG) run_warp<NG_BIG>(m, sm, sidx[ring], lane, r, py, Kr);
    else              run_warp<NG_SML>(m, sm, sidx[ring], lane, r, py, Kr);

    // Final fold: butterfly min per angle, REDG.MAX into g_keys.
    #pragma unroll
    for (int a = 0; a < NANG; a++) {
        float x = m[a];
        #pragma unroll
        for (int o = 16; o > 0; o >>= 1)
            x = fminf(x, __shfl_xor_sync(0xffffffffu, x, o));
        if (lane == (a & 31))
            atomicMax(&g_keys[pbase + a], enc_f32(-x));
    }

    // ---- last-block finalize (fused) ----
    __threadfence();
    if (tid == 0)
        is_last = (atomicAdd(&g_count, 1u) == (unsigned)(NBLK - 1));
    __syncthreads();
    if (!is_last) return;
    __threadfence();

    uint4* keys4 = (uint4*)g_keys;
    const int n4 = (NB * NPTS) / 4;     // 2880
    float s = 0.0f;
    for (int i = tid; i < n4; i += TPB) {
        uint4 k = keys4[i];
        s += fmaxf(-dec_f32(k.x), 0.0f);
        s += fmaxf(-dec_f32(k.y), 0.0f);
        s += fmaxf(-dec_f32(k.z), 0.0f);
        s += fmaxf(-dec_f32(k.w), 0.0f);
    }
    #pragma unroll
    for (int o = 16; o > 0; o >>= 1) s += __shfl_down_sync(0xffffffffu, s, o);
    if (lane == 0) wsum[ring] = s;
    __syncthreads();
    if (tid == 0) {
        float tot = 0.0f;
        #pragma unroll
        for (int w = 0; w < NRINGS; w++) tot += wsum[w];
        out[0] = tot / (float)(NB * NPTS);
    }
    __syncthreads();   // all g_keys reads complete before reset

    const uint4 z4 = make_uint4(0u, 0u, 0u, 0u);
    for (int i = tid; i < n4; i += TPB) keys4[i] = z4;
    if (tid == 0) g_count = 0u;
}

extern "C" void kernel_launch(void* const* d_in, const int* in_sizes, int n_in,
                              void* d_out, int out_size) {
    const float* pred   = (const float*)d_in[0];   // (32, 10)
    const float* target = (const float*)d_in[1];   // (32, 16384, 3)
    float* out = (float*)d_out;

    chamfer_fused_kernel<<<NBLK, TPB>>>(pred, target, out);
}

// round 16
// speedup vs baseline: 1.0714x; 1.0703x over previous
#include <cuda_runtime.h>
#include <cuda_bf16.h>
#include <cstdint>

#define NB      32
#define NRINGS  10
#define NANG    36
#define NPTS    (NRINGS * NANG)     // 360
#define NTGT    16384
#define TPB     (NRINGS * 32)       // 320 threads: warp = ring
#define NBLK    444                 // 148 SMs x 3 resident -> one wave
#define NBIG    392                 // batches 0..27: 14 blocks x 37 groups
#define NG_BIG  37                  // 14*37*32 >= 16384 (dup-clamped tail)
#define NG_SML  40                  // 13*40*32 >= 16384
#define MAXT    (NG_SML * 32)       // 1280 staged targets

// Per-(batch,point) running MAX of k = ~bits(d2 + 1). d2+1 > 0 always, so bits
// are monotone in d2 and ~bits is monotone-DEcreasing -> max(k) = min(d2).
// Sentinel = 0 (static zero-init); last block resets after the reduce.
__device__ unsigned int g_keys[NB * NPTS];
__device__ unsigned int g_count;

// cos/sin magnitudes (10..40 deg); all appear as FFMA immediates.
#define K_C1 0.9848077530f
#define K_S1 0.1736481777f
#define K_C2 0.9396926208f
#define K_S2 0.3420201433f
#define K_C3 0.8660254038f
#define K_S3 0.5f
#define K_C4 0.7660444431f
#define K_S4 0.6427876097f

// Paired angles (a, 36-a): shared-cos FFMA, then +/-S*V. Constants = FFMA imms.
#define PAIR2(IA, IB, CV, SV)                        \
    { float P = fmaf(CV, U, Acc);                    \
      m[IA] = fminf(m[IA], fmaf( SV, V, P));         \
      m[IB] = fminf(m[IB], fmaf(-SV, V, P)); }

// Full 36-angle evaluation on Kr-free partial Acc. 87 instr/target.
__device__ __forceinline__ void eval36(float m[NANG], float U, float V, float Acc) {
    m[ 0] = fminf(m[ 0], Acc + U);
    m[18] = fminf(m[18], Acc - U);
    m[ 9] = fminf(m[ 9], Acc + V);
    m[27] = fminf(m[27], Acc - V);
    PAIR2( 1, 35,  K_C1, K_S1)
    PAIR2( 2, 34,  K_C2, K_S2)
    PAIR2( 3, 33,  K_C3, K_S3)
    PAIR2( 4, 32,  K_C4, K_S4)
    PAIR2( 5, 31,  K_S4, K_C4)
    PAIR2( 6, 30,  K_S3, K_C3)
    PAIR2( 7, 29,  K_S2, K_C2)
    PAIR2( 8, 28,  K_S1, K_C1)
    PAIR2(10, 26, -K_S1, K_C1)
    PAIR2(11, 25, -K_S2, K_C2)
    PAIR2(12, 24, -K_S3, K_C3)
    PAIR2(13, 23, -K_S4, K_C4)
    PAIR2(14, 22, -K_C4, K_S4)
    PAIR2(15, 21, -K_C3, K_S3)
    PAIR2(16, 20, -K_C2, K_S2)
    PAIR2(17, 19, -K_C1, K_S1)
}

// Mainloop with compile-time trip count; Kr excluded from Acc (added at fold).
template<int NG>
__device__ __forceinline__ void run_tile(float m[NANG], const float4* __restrict__ sm,
                                         int lane, float r, float py)
{
    #pragma unroll 2
    for (int it = 0; it < NG; it++) {
        float4 v  = sm[it * 32 + lane];
        float Acc = fmaf(py, v.y, v.w);   // Kr folded in after the loop
        float U   = r * v.x;
        float V   = r * v.z;
        eval36(m, U, V, Acc);
    }
}

__global__ void __launch_bounds__(TPB)
chamfer_fused_kernel(const float* __restrict__ pred,
                     const float* __restrict__ target,
                     float* __restrict__ out)
{
    __shared__ float4 sm[MAXT];
    __shared__ float  wsum[NRINGS];
    __shared__ unsigned int is_last;

    const int bid = blockIdx.x;
    const int tid = threadIdx.x;

    // Block -> (batch, within-batch tile). Every block is single-batch.
    int batch, wb, ng;
    if (bid < NBIG) { batch = bid / 14;            wb = bid - batch * 14;  ng = NG_BIG; }
    else            { int e = bid - NBIG; int q = e / 13;
                      batch = 28 + q;              wb = e - q * 13;        ng = NG_SML; }

    const int start = wb * ng * 32;     // within-batch target start (32-mult)

    // Vectorized staging: thread i handles targets [4ci, 4ci+4) via 3 LDG.128.
    // (batch*NTGT + start)*3 floats is 16B-aligned. Clamp at THREAD granularity
    // so the xyz triple alignment is preserved (duplicates = real targets).
    {
        const int nThreads = ng * 8;                       // n/4
        if (tid < nThreads) {
            const int iMax = ((NTGT - start) >> 2) - 1;    // last valid 4-target slot
            const int ci   = min(tid, iMax);
            const float4* gp = (const float4*)(target + ((size_t)batch * NTGT + start) * 3);
            float4 f0 = gp[3 * ci + 0];
            float4 f1 = gp[3 * ci + 1];
            float4 f2 = gp[3 * ci + 2];
            // targets: (f0.x,f0.y,f0.z) (f0.w,f1.x,f1.y) (f1.z,f1.w,f2.x) (f2.y,f2.z,f2.w)
            float txs[4] = {f0.x, f0.w, f1.z, f2.y};
            float tys[4] = {f0.y, f1.x, f1.w, f2.z};
            float tzs[4] = {f0.z, f1.y, f2.x, f2.w};
            #pragma unroll
            for (int k = 0; k < 4; k++) {
                float tx = txs[k], ty = tys[k], tz = tzs[k];
                float t2 = tx * tx + ty * ty + tz * tz;
                sm[4 * tid + k] = make_float4(2.0f * tx - 0.08f, -2.0f * ty, -2.0f * tz,
                                              fmaf(-0.08f, tx, t2));
            }
        }
    }
    __syncthreads();

    const int ring = tid >> 5;
    const int lane = tid & 31;

    const float r    = pred[batch * NRINGS + ring];
    const float py   = 0.15f * (float)ring - 0.7f;
    const float KrP1 = fmaf(r, r, fmaf(py, py, 1.0016f));   // Kr + 1.0
    const unsigned int pbase = (unsigned)(batch * NPTS + ring * NANG);
    const float INF = __int_as_float(0x7f800000);

    float m[NANG];
    #pragma unroll
    for (int a = 0; a < NANG; a++) m[a] = INF;

    if (ng == NG_BIG) run_tile<NG_BIG>(m, sm, lane, r, py);
    else              run_tile<NG_SML>(m, sm, lane, r, py);

    // Fold: k = ~bits(m'[a] + Kr + 1) (monotone-decreasing in d2);
    // warp-min via REDUX.MAX.U32; cross-block min via RED.MAX.
    #pragma unroll
    for (int a = 0; a < NANG; a++) {
        unsigned k = ~__float_as_uint(m[a] + KrP1);
        unsigned w = __reduce_max_sync(0xffffffffu, k);
        if (lane == (a & 31))
            atomicMax(&g_keys[pbase + a], w);
    }

    // ---- last-block finalize (fused; no second kernel) ----
    __threadfence();
    if (tid == 0)
        is_last = (atomicAdd(&g_count, 1u) == (unsigned)(NBLK - 1));
    __syncthreads();
    if (!is_last) return;
    __threadfence();

    uint4* keys4 = (uint4*)g_keys;
    const int n4 = (NB * NPTS) / 4;     // 2880
    float s = 0.0f;
    for (int i = tid; i < n4; i += TPB) {
        uint4 k = keys4[i];
        s += fmaxf(__uint_as_float(~k.x) - 1.0f, 0.0f);
        s += fmaxf(__uint_as_float(~k.y) - 1.0f, 0.0f);
        s += fmaxf(__uint_as_float(~k.z) - 1.0f, 0.0f);
        s += fmaxf(__uint_as_float(~k.w) - 1.0f, 0.0f);
    }
    #pragma unroll
    for (int o = 16; o > 0; o >>= 1) s += __shfl_down_sync(0xffffffffu, s, o);
    if (lane == 0) wsum[ring] = s;
    __syncthreads();
    if (tid == 0) {
        float tot = 0.0f;
        #pragma unroll
        for (int w = 0; w < NRINGS; w++) tot += wsum[w];
        out[0] = tot / (float)(NB * NPTS);
    }
    __syncthreads();   // all g_keys reads complete before reset

    const uint4 z4 = make_uint4(0u, 0u, 0u, 0u);
    for (int i = tid; i < n4; i += TPB) keys4[i] = z4;
    if (tid == 0) g_count = 0u;
}

extern "C" void kernel_launch(void* const* d_in, const int* in_sizes, int n_in,
                              void* d_out, int out_size) {
    const float* pred   = (const float*)d_in[0];   // (32, 10)
    const float* target = (const float*)d_in[1];   // (32, 16384, 3)
    float* out = (float*)d_out;

    chamfer_fused_kernel<<<NBLK, TPB>>>(pred, target, out);
}

// round 17
// speedup vs baseline: 1.0991x; 1.0259x over previous
#include <cuda_runtime.h>
#include <cuda_bf16.h>
#include <cstdint>

#define NB      32
#define NRINGS  10
#define NANG    36
#define NPTS    (NRINGS * NANG)     // 360
#define NTGT    16384
#define TPB     (NRINGS * 32)       // 320 threads: warp = ring
#define NBLK    444                 // 148 SMs x 3 resident -> one wave
#define NBIG    392                 // batches 0..27: 14 blocks x 37 groups
#define NG_BIG  37                  // 14*37*32 >= 16384 (dup-clamped tail)
#define NG_SML  40                  // 13*40*32 >= 16384
#define MAXT    (NG_SML * 32)       // 1280 staged targets

// Per-(batch,point) running MAX of k = ~bits(d2 + 1). d2+1 > 0 always, so bits
// are monotone in d2 and ~bits is monotone-DEcreasing -> max(k) = min(d2).
// Sentinel = 0 (static zero-init); last block resets after the reduce.
__device__ unsigned int g_keys[NB * NPTS];
__device__ unsigned int g_count;

// cos/sin magnitudes (10..40 deg); all appear as FFMA immediates.
#define K_C1 0.9848077530f
#define K_S1 0.1736481777f
#define K_C2 0.9396926208f
#define K_S2 0.3420201433f
#define K_C3 0.8660254038f
#define K_S3 0.5f
#define K_C4 0.7660444431f
#define K_S4 0.6427876097f

// Quad (a, 36-a, 18+a, 18-a):
//   P    = fma(C,U,Acc)                  (shared cos)
//   d_a  = fma( S,V,P)   -> m[a]
//   d_-a = fma(-S,V,P)   -> m[36-a]
//   x_{18+a} = -x_a      -> d = 2*Acc - d_a   (1 FADD, neg modifier)
//   x_{18-a} = -x_{36-a} -> d = 2*Acc - d_-a
// 9 instr / 4 angles.
#define QUAD4(IA, CV, SV)                                  \
    { float P  = fmaf(CV, U, Acc);                         \
      float da = fmaf( SV, V, P);                          \
      float db = fmaf(-SV, V, P);                          \
      m[IA]      = fminf(m[IA],      da);                  \
      m[36-IA]   = fminf(m[36-IA],   db);                  \
      m[18+IA]   = fminf(m[18+IA],   Acc2 - da);           \
      m[18-IA]   = fminf(m[18-IA],   Acc2 - db); }

// Full 36-angle evaluation on Kr-free partial Acc. 80 eval instr/target.
__device__ __forceinline__ void eval36(float m[NANG], float U, float V,
                                       float Acc, float Acc2) {
    // axis angles: 0/180 via U, 90/270 via V (opposite-angle FADD trick)
    float t0 = Acc + U;
    m[ 0] = fminf(m[ 0], t0);
    m[18] = fminf(m[18], Acc2 - t0);
    float t9 = Acc + V;
    m[ 9] = fminf(m[ 9], t9);
    m[27] = fminf(m[27], Acc2 - t9);
    QUAD4(1, K_C1, K_S1)
    QUAD4(2, K_C2, K_S2)
    QUAD4(3, K_C3, K_S3)
    QUAD4(4, K_C4, K_S4)
    QUAD4(5, K_S4, K_C4)   // cos50 = sin40
    QUAD4(6, K_S3, K_C3)
    QUAD4(7, K_S2, K_C2)
    QUAD4(8, K_S1, K_C1)
}

// Mainloop with compile-time trip count; Kr excluded from Acc (added at fold).
template<int NG>
__device__ __forceinline__ void run_tile(float m[NANG], const float4* __restrict__ sm,
                                         int lane, float r, float py)
{
    #pragma unroll 2
    for (int it = 0; it < NG; it++) {
        float4 v   = sm[it * 32 + lane];
        float Acc  = fmaf(py, v.y, v.w);   // Kr folded in after the loop
        float Acc2 = Acc + Acc;
        float U    = r * v.x;
        float V    = r * v.z;
        eval36(m, U, V, Acc, Acc2);
    }
}

__global__ void __launch_bounds__(TPB)
chamfer_fused_kernel(const float* __restrict__ pred,
                     const float* __restrict__ target,
                     float* __restrict__ out)
{
    __shared__ float4 sm[MAXT];
    __shared__ float  wsum[NRINGS];
    __shared__ unsigned int is_last;

    const int bid = blockIdx.x;
    const int tid = threadIdx.x;

    // Block -> (batch, within-batch tile). Every block is single-batch.
    int batch, wb, ng;
    if (bid < NBIG) { batch = bid / 14;            wb = bid - batch * 14;  ng = NG_BIG; }
    else            { int e = bid - NBIG; int q = e / 13;
                      batch = 28 + q;              wb = e - q * 13;        ng = NG_SML; }

    const int start = wb * ng * 32;     // within-batch target start (32-mult)

    // Vectorized staging: thread i handles targets [4ci, 4ci+4) via 3 LDG.128.
    // Clamp at THREAD granularity so xyz triple alignment is preserved
    // (duplicates are real targets; min-safe).
    {
        const int nThreads = ng * 8;                       // n/4
        if (tid < nThreads) {
            const int iMax = ((NTGT - start) >> 2) - 1;    // last valid 4-target slot
            const int ci   = min(tid, iMax);
            const float4* gp = (const float4*)(target + ((size_t)batch * NTGT + start) * 3);
            float4 f0 = gp[3 * ci + 0];
            float4 f1 = gp[3 * ci + 1];
            float4 f2 = gp[3 * ci + 2];
            float txs[4] = {f0.x, f0.w, f1.z, f2.y};
            float tys[4] = {f0.y, f1.x, f1.w, f2.z};
            float tzs[4] = {f0.z, f1.y, f2.x, f2.w};
            #pragma unroll
            for (int k = 0; k < 4; k++) {
                float tx = txs[k], ty = tys[k], tz = tzs[k];
                float t2 = tx * tx + ty * ty + tz * tz;
                sm[4 * tid + k] = make_float4(2.0f * tx - 0.08f, -2.0f * ty, -2.0f * tz,
                                              fmaf(-0.08f, tx, t2));
            }
        }
    }
    __syncthreads();

    const int ring = tid >> 5;
    const int lane = tid & 31;

    const float r    = pred[batch * NRINGS + ring];
    const float py   = 0.15f * (float)ring - 0.7f;
    const float KrP1 = fmaf(r, r, fmaf(py, py, 1.0016f));   // Kr + 1.0
    const unsigned int pbase = (unsigned)(batch * NPTS + ring * NANG);
    const float INF = __int_as_float(0x7f800000);

    float m[NANG];
    #pragma unroll
    for (int a = 0; a < NANG; a++) m[a] = INF;

    if (ng == NG_BIG) run_tile<NG_BIG>(m, sm, lane, r, py);
    else              run_tile<NG_SML>(m, sm, lane, r, py);

    // Fold: k = ~bits(m'[a] + Kr + 1) (monotone-decreasing in d2);
    // warp-min via REDUX.MAX.U32; cross-block min via RED.MAX.
    #pragma unroll
    for (int a = 0; a < NANG; a++) {
        unsigned k = ~__float_as_uint(m[a] + KrP1);
        unsigned w = __reduce_max_sync(0xffffffffu, k);
        if (lane == (a & 31))
            atomicMax(&g_keys[pbase + a], w);
    }

    // ---- last-block finalize (fused; no second kernel) ----
    __threadfence();
    if (tid == 0)
        is_last = (atomicAdd(&g_count, 1u) == (unsigned)(NBLK - 1));
    __syncthreads();
    if (!is_last) return;
    __threadfence();

    uint4* keys4 = (uint4*)g_keys;
    const int n4 = (NB * NPTS) / 4;     // 2880
    float s = 0.0f;
    for (int i = tid; i < n4; i += TPB) {
        uint4 k = keys4[i];
        s += fmaxf(__uint_as_float(~k.x) - 1.0f, 0.0f);
        s += fmaxf(__uint_as_float(~k.y) - 1.0f, 0.0f);
        s += fmaxf(__uint_as_float(~k.z) - 1.0f, 0.0f);
        s += fmaxf(__uint_as_float(~k.w) - 1.0f, 0.0f);
    }
    #pragma unroll
    for (int o = 16; o > 0; o >>= 1) s += __shfl_down_sync(0xffffffffu, s, o);
    if (lane == 0) wsum[ring] = s;
    __syncthreads();
    if (tid == 0) {
        float tot = 0.0f;
        #pragma unroll
        for (int w = 0; w < NRINGS; w++) tot += wsum[w];
        out[0] = tot / (float)(NB * NPTS);
    }
    __syncthreads();   // all g_keys reads complete before reset

    const uint4 z4 = make_uint4(0u, 0u, 0u, 0u);
    for (int i = tid; i < n4; i += TPB) keys4[i] = z4;
    if (tid == 0) g_count = 0u;
}

extern "C" void kernel_launch(void* const* d_in, const int* in_sizes, int n_in,
                              void* d_out, int out_size) {
    const float* pred   = (const float*)d_in[0];   // (32, 10)
    const float* target = (const float*)d_in[1];   // (32, 16384, 3)
    float* out = (float*)d_out;

    chamfer_fused_kernel<<<NBLK, TPB>>>(pred, target, out);
}